// round 5
// baseline (speedup 1.0000x reference)
#include <cuda_runtime.h>
#include <cuda_bf16.h>
#include <stdint.h>
#include <math.h>

// ---------------------------------------------------------------- constants
#define BATCH   2
#define NQ      16384
#define NATOMS  1024
#define KDIM    256
#define ODIM    256
#define NROWS   (BATCH * NQ)
#define OMEGA0  30.0f
#define EPSD    1e-4f

#define BM      128
#define BN      128
#define BKC     32
#define NCHUNK  (KDIM / BKC)     // 8

#define ROWB    80               // conflict-free pitch for ldmatrix
#define OFF_AH  0
#define OFF_AL  10240
#define OFF_BH  20480
#define OFF_BL  30720
#define STAGE   40960            // two stages: 0, 40960
#define OFF_ATOM  81920          // 1024 float4
#define OFF_OMEGA 98304          // 128 floats
#define OFF_PART  98816          // 256 floats
#define SM_BYTES  100352
#define EPI_STRIDE 132           // floats

static __device__ __nv_bfloat16 g_Whi[ODIM * KDIM];
static __device__ __nv_bfloat16 g_Wlo[ODIM * KDIM];
static __device__ float4        g_atom4[BATCH * NATOMS];

// ---------------------------------------------------------------- helpers
__device__ __forceinline__ uint32_t smem_u32(const void* p) {
    uint32_t a;
    asm("{ .reg .u64 t; cvta.to.shared.u64 t, %1; cvt.u32.u64 %0, t; }" : "=r"(a) : "l"(p));
    return a;
}
__device__ __forceinline__ void sts_u4(uint32_t a, uint32_t x, uint32_t y,
                                       uint32_t z, uint32_t w) {
    asm volatile("st.shared.v4.b32 [%0], {%1,%2,%3,%4};" :: "r"(a), "r"(x), "r"(y), "r"(z), "r"(w));
}
__device__ __forceinline__ void cp16(uint32_t dst, const void* src) {
    asm volatile("cp.async.cg.shared.global [%0], [%1], 16;" :: "r"(dst), "l"(src));
}
#define CP_COMMIT() asm volatile("cp.async.commit_group;")
#define CP_WAIT0()  asm volatile("cp.async.wait_group 0;")
#define CP_WAIT1()  asm volatile("cp.async.wait_group 1;")

#define LDSM4(r, a) \
    asm volatile("ldmatrix.sync.aligned.m8n8.x4.shared.b16 {%0,%1,%2,%3}, [%4];" \
        : "=r"((r)[0]), "=r"((r)[1]), "=r"((r)[2]), "=r"((r)[3]) : "r"(a))

__device__ __forceinline__ void mma_bf16(float* c, const uint32_t* a,
                                         uint32_t b0, uint32_t b1) {
    asm volatile(
        "mma.sync.aligned.m16n8k16.row.col.f32.bf16.bf16.f32 "
        "{%0,%1,%2,%3}, {%4,%5,%6,%7}, {%8,%9}, {%0,%1,%2,%3};"
        : "+f"(c[0]), "+f"(c[1]), "+f"(c[2]), "+f"(c[3])
        : "r"(a[0]), "r"(a[1]), "r"(a[2]), "r"(a[3]), "r"(b0), "r"(b1));
}
__device__ __forceinline__ void split2(float x, float y, uint32_t& h, uint32_t& l) {
    __nv_bfloat16 bx = __float2bfloat16(x), by = __float2bfloat16(y);
    h = (uint32_t)__bfloat16_as_ushort(bx) | ((uint32_t)__bfloat16_as_ushort(by) << 16);
    float rx = x - __bfloat162float(bx), ry = y - __bfloat162float(by);
    __nv_bfloat16 cx = __float2bfloat16(rx), cy = __float2bfloat16(ry);
    l = (uint32_t)__bfloat16_as_ushort(cx) | ((uint32_t)__bfloat16_as_ushort(cy) << 16);
}

// ---------------------------------------------------------------- prep
__global__ __launch_bounds__(256)
void prep_kernel(const float* __restrict__ W, const float* __restrict__ atoms)
{
    int b = blockIdx.x;
    if (b < (ODIM * KDIM) / 256) {
        int i = b * 256 + threadIdx.x;
        float w = W[i];
        __nv_bfloat16 h = __float2bfloat16(w);
        g_Whi[i] = h;
        g_Wlo[i] = __float2bfloat16(w - __bfloat162float(h));
    } else {
        int i = (b - (ODIM * KDIM) / 256) * 256 + threadIdx.x;
        float ax = atoms[i*3], ay = atoms[i*3+1], az = atoms[i*3+2];
        g_atom4[i] = make_float4(ax, ay, az, fmaf(ax, ax, fmaf(ay, ay, az*az)));
    }
}

// ---------------------------------------------------------------- fused kernel
__global__ __launch_bounds__(256, 2)
void siren_fused(const float* __restrict__ X, const float* __restrict__ Q,
                 const float* __restrict__ bias,
                 const float* __restrict__ fw1, const float* __restrict__ fb1,
                 const float* __restrict__ fw2, const float* __restrict__ fb2,
                 float* __restrict__ out)
{
    extern __shared__ char sb[];
    const uint32_t sbase = smem_u32(sb);

    const int tid  = threadIdx.x;
    const int lane = tid & 31;
    const int wid  = tid >> 5;
    const int gRow0 = (blockIdx.x >> 1) * BM;
    const int gCol0 = (blockIdx.x & 1) * BN;
    const int batch = (gRow0 >= NQ) ? 1 : 0;

    const int warpM = (wid & 3) * 32;       // 4 M-groups
    const int warpN = (wid >> 2) * 64;      // 2 N-groups
    const int lr = lane >> 2;
    const int lc = (lane & 3) * 2;
    const int l7 = lane & 7, g = lane >> 3;
    const uint32_t aoff = (uint32_t)((warpM + l7 + (g & 1) * 8) * ROWB + ((g >> 1) & 1) * 16);
    const uint32_t boff = (uint32_t)((warpN + l7 + (g >> 1) * 8) * ROWB + (g & 1) * 16);

    // ---- prologue: atoms (group A), W chunk0 (group B) ----
    {
        const float4* ap = g_atom4 + batch * NATOMS;
#pragma unroll
        for (int i = 0; i < 4; ++i) {
            int lin = tid + i * 256;
            cp16(sbase + OFF_ATOM + lin * 16, ap + lin);
        }
    }
    CP_COMMIT();
#pragma unroll
    for (int i = 0; i < 2; ++i) {
        int lin = tid + i * 256;            // 0..511
        int n = lin >> 2, qd = lin & 3;
        uint32_t d = sbase + n * ROWB + qd * 16;
        const int gsrc = (gCol0 + n) * KDIM + qd * 8;
        cp16(d + OFF_BH, g_Whi + gsrc);
        cp16(d + OFF_BL, g_Wlo + gsrc);
    }
    CP_COMMIT();

    const int xr = tid >> 1, xh = tid & 1;
    const float* Xrow = X + (size_t)(gRow0 + xr) * KDIM + xh * 16;
    float4 v0 = *(const float4*)(Xrow);
    float4 v1 = *(const float4*)(Xrow + 4);
    float4 v2 = *(const float4*)(Xrow + 8);
    float4 v3 = *(const float4*)(Xrow + 12);

    CP_WAIT1();                 // atoms landed
    __syncthreads();

    // ---- omega min-dist scan: 2 threads per query ----
    {
        const int qi = tid & 127, qq = tid >> 7;
        const float* qp = Q + (size_t)(gRow0 + qi) * 3;
        float qx = qp[0], qy = qp[1], qz = qp[2];
        float nqx = -2.f * qx, nqy = -2.f * qy, nqz = -2.f * qz;
        const float4* sAt = (const float4*)(sb + OFF_ATOM) + qq * 512;
        float md = 3.4e38f;
#pragma unroll 4
        for (int j = 0; j < 512; ++j) {
            float4 a = sAt[j];
            md = fminf(md, fmaf(a.x, nqx, fmaf(a.y, nqy, fmaf(a.z, nqz, a.w))));
        }
        ((float*)(sb + OFF_PART))[qq * 128 + qi] = md;
    }

    // ---- store X chunk0 ----
    {
        uint32_t h[8], l[8];
        split2(v0.x, v0.y, h[0], l[0]); split2(v0.z, v0.w, h[1], l[1]);
        split2(v1.x, v1.y, h[2], l[2]); split2(v1.z, v1.w, h[3], l[3]);
        split2(v2.x, v2.y, h[4], l[4]); split2(v2.z, v2.w, h[5], l[5]);
        split2(v3.x, v3.y, h[6], l[6]); split2(v3.z, v3.w, h[7], l[7]);
        uint32_t aB = sbase + xr * ROWB + xh * 32;
        sts_u4(aB + OFF_AH,      h[0], h[1], h[2], h[3]);
        sts_u4(aB + OFF_AH + 16, h[4], h[5], h[6], h[7]);
        sts_u4(aB + OFF_AL,      l[0], l[1], l[2], l[3]);
        sts_u4(aB + OFF_AL + 16, l[4], l[5], l[6], l[7]);
    }
    CP_WAIT0();                 // W chunk0 landed
    __syncthreads();            // also publishes omega partials

    // ---- freq-net + omega finalize ----
    if (tid < 128) {
        const float* part = (const float*)(sb + OFF_PART);
        float m = fminf(part[tid], part[128 + tid]);
        const float* qp = Q + (size_t)(gRow0 + tid) * 3;
        float qx = qp[0], qy = qp[1], qz = qp[2];
        float qsq = fmaf(qx, qx, fmaf(qy, qy, qz * qz));
        float mind = sqrtf(fmaxf(m + qsq, EPSD));
        float ls = fb2[0];
#pragma unroll
        for (int j = 0; j < 16; ++j) {
            float z = fmaf(fw1[3*j], qx, fmaf(fw1[3*j+1], qy, fmaf(fw1[3*j+2], qz, fb1[j])));
            float sp = fmaxf(z, 0.0f) + log1pf(expf(-fabsf(z)));
            ls = fmaf(fw2[j], sp, ls);
        }
        ls = fminf(fmaxf(ls, 0.0f), 5.0f);
        ((float*)(sb + OFF_OMEGA))[tid] = OMEGA0 * (1.0f + ls * expf(-mind));
    }

    float acc[2][8][4];
#pragma unroll
    for (int i = 0; i < 2; ++i)
#pragma unroll
        for (int j = 0; j < 8; ++j)
#pragma unroll
            for (int k = 0; k < 4; ++k) acc[i][j][k] = 0.0f;

    // ---- main loop: LDG -> cp.async -> COMPUTE -> STS -> wait/sync ----
#pragma unroll 1
    for (int c = 0; c < NCHUNK; ++c) {
        const uint32_t st = sbase + (uint32_t)(c & 1) * STAGE;
        const bool more = (c + 1 < NCHUNK);
        if (more) {
            const float* Xn = Xrow + (c + 1) * BKC;
            v0 = *(const float4*)(Xn);
            v1 = *(const float4*)(Xn + 4);
            v2 = *(const float4*)(Xn + 8);
            v3 = *(const float4*)(Xn + 12);
            const int ko = (c + 1) * BKC;
            uint32_t dstS = sbase + (uint32_t)((c + 1) & 1) * STAGE;
#pragma unroll
            for (int i = 0; i < 2; ++i) {
                int lin = tid + i * 256;
                int n = lin >> 2, qd = lin & 3;
                uint32_t d = dstS + n * ROWB + qd * 16;
                const int gsrc = (gCol0 + n) * KDIM + ko + qd * 8;
                cp16(d + OFF_BH, g_Whi + gsrc);
                cp16(d + OFF_BL, g_Wlo + gsrc);
            }
            CP_COMMIT();
        }

        // compute chunk c
#pragma unroll
        for (int ks = 0; ks < 2; ++ks) {
            uint32_t ah[2][4], al[2][4], bq[4][4];
            const uint32_t ab = st + aoff + ks * 32;
            const uint32_t bb = st + boff + ks * 32;
            LDSM4(ah[0], ab + OFF_AH);
            LDSM4(ah[1], ab + OFF_AH + 16 * ROWB);
            LDSM4(al[0], ab + OFF_AL);
            LDSM4(al[1], ab + OFF_AL + 16 * ROWB);
#pragma unroll
            for (int p = 0; p < 4; ++p) LDSM4(bq[p], bb + OFF_BH + p * 16 * ROWB);
            // pass 1: hi*hi  (acc reuse distance = 16)
#pragma unroll
            for (int mt = 0; mt < 2; ++mt)
#pragma unroll
                for (int p = 0; p < 4; ++p) {
                    mma_bf16(acc[mt][2*p],   ah[mt], bq[p][0], bq[p][1]);
                    mma_bf16(acc[mt][2*p+1], ah[mt], bq[p][2], bq[p][3]);
                }
            // pass 2: lo*hi
#pragma unroll
            for (int mt = 0; mt < 2; ++mt)
#pragma unroll
                for (int p = 0; p < 4; ++p) {
                    mma_bf16(acc[mt][2*p],   al[mt], bq[p][0], bq[p][1]);
                    mma_bf16(acc[mt][2*p+1], al[mt], bq[p][2], bq[p][3]);
                }
            // pass 3: hi*lo (reuse bq registers)
#pragma unroll
            for (int p = 0; p < 4; ++p) LDSM4(bq[p], bb + OFF_BL + p * 16 * ROWB);
#pragma unroll
            for (int mt = 0; mt < 2; ++mt)
#pragma unroll
                for (int p = 0; p < 4; ++p) {
                    mma_bf16(acc[mt][2*p],   ah[mt], bq[p][0], bq[p][1]);
                    mma_bf16(acc[mt][2*p+1], ah[mt], bq[p][2], bq[p][3]);
                }
        }

        if (more) {
            uint32_t h[8], l[8];
            split2(v0.x, v0.y, h[0], l[0]); split2(v0.z, v0.w, h[1], l[1]);
            split2(v1.x, v1.y, h[2], l[2]); split2(v1.z, v1.w, h[3], l[3]);
            split2(v2.x, v2.y, h[4], l[4]); split2(v2.z, v2.w, h[5], l[5]);
            split2(v3.x, v3.y, h[6], l[6]); split2(v3.z, v3.w, h[7], l[7]);
            uint32_t aB = sbase + (uint32_t)((c + 1) & 1) * STAGE + xr * ROWB + xh * 32;
            sts_u4(aB + OFF_AH,      h[0], h[1], h[2], h[3]);
            sts_u4(aB + OFF_AH + 16, h[4], h[5], h[6], h[7]);
            sts_u4(aB + OFF_AL,      l[0], l[1], l[2], l[3]);
            sts_u4(aB + OFF_AL + 16, l[4], l[5], l[6], l[7]);
            CP_WAIT0();
            __syncthreads();
        }
    }
    __syncthreads();    // stage smem free for epilogue

    // ---- epilogue: sin(omega*(acc+bias)) -> SMEM -> coalesced STG ----
    float* stg = (float*)sb;
    const float* omg = (const float*)(sb + OFF_OMEGA);
#pragma unroll
    for (int mt = 0; mt < 2; ++mt) {
        int r0 = warpM + mt * 16 + lr;
        float o0 = omg[r0], o1 = omg[r0 + 8];
#pragma unroll
        for (int nt = 0; nt < 8; ++nt) {
            int c0 = warpN + nt * 8 + lc;
            float b0 = __ldg(bias + gCol0 + c0), b1 = __ldg(bias + gCol0 + c0 + 1);
            float* a = acc[mt][nt];
            *(float2*)(stg + r0 * EPI_STRIDE + c0) =
                make_float2(__sinf(o0 * (a[0] + b0)), __sinf(o0 * (a[1] + b1)));
            *(float2*)(stg + (r0 + 8) * EPI_STRIDE + c0) =
                make_float2(__sinf(o1 * (a[2] + b0)), __sinf(o1 * (a[3] + b1)));
        }
    }
    __syncthreads();
#pragma unroll
    for (int i = 0; i < 16; ++i) {
        int lin = tid + i * 256;
        int r = lin >> 5, c4 = (lin & 31) * 4;
        *(float4*)(out + (size_t)(gRow0 + r) * ODIM + gCol0 + c4) =
            *(const float4*)(stg + r * EPI_STRIDE + c4);
    }
}

// ---------------------------------------------------------------- launch
extern "C" void kernel_launch(void* const* d_in, const int* in_sizes, int n_in,
                              void* d_out, int out_size)
{
    const float* x     = (const float*)d_in[0];
    const float* q     = (const float*)d_in[1];
    const float* atoms = (const float*)d_in[2];
    const float* W     = (const float*)d_in[3];
    const float* bias  = (const float*)d_in[4];
    const float* fw1   = (const float*)d_in[5];
    const float* fb1   = (const float*)d_in[6];
    const float* fw2   = (const float*)d_in[7];
    const float* fb2   = (const float*)d_in[8];
    float* out = (float*)d_out;
    (void)in_sizes; (void)n_in; (void)out_size;

    cudaFuncSetAttribute(siren_fused, cudaFuncAttributeMaxDynamicSharedMemorySize, SM_BYTES);

    prep_kernel<<<(ODIM * KDIM) / 256 + (BATCH * NATOMS) / 256, 256>>>(W, atoms);
    siren_fused<<<(NROWS / BM) * (ODIM / BN), 256, SM_BYTES>>>(x, q, bias, fw1, fb1, fw2, fb2, out);
}